// round 6
// baseline (speedup 1.0000x reference)
#include <cuda_runtime.h>
#include <cstdint>

#define T_STEPS 512
#define BATCH   32
#define HID     512
#define LN_EPS  1e-5f
#define NBLK    128          // recurrent grid (64 CTAs per direction)
#define HP      516          // hsh pitch (floats): conflict-free, 16B-aligned rows
#define WP      516          // Wsh pitch (floats): conflict-free col-major weight rows

// ---- packed fp32x2 helpers (SASS FFMA2 — ptxas never auto-generates this) ----
#define FMA2(acc, a, b) \
    asm("fma.rn.f32x2 %0, %1, %2, %0;" : "+l"(acc) : "l"(a), "l"(b))

__device__ __forceinline__ float2 unpk(unsigned long long v) {
    float2 r;
    asm("mov.b64 {%0, %1}, %2;" : "=f"(r.x), "=f"(r.y) : "l"(v));
    return r;
}

// ---------------- scratch (static device globals; no allocation) ----------------
__device__ float    g_ax[(size_t)2 * 512 * 32 * 1536];   // LN(x@Wx+bx) per dir
__device__ float    g_seq[(size_t)2 * 512 * 32 * 512];   // layer-0 outputs (fwd, bwd)
__device__ float    g_h[2 * 32 * 512];                   // current hidden state per dir
__device__ float    g_stats[2 * 2 * 32 * 3 * 2];         // [parity][dir][b][gate][sum,sq]
__device__ unsigned g_bar;                               // grid barrier counter

// ============================================================================
// Input GEMM: 128x128x16 fp32 tile, 256 threads, 8x8 microtile via FFMA2.
// B tile stored DUPLICATED in SMEM so both FFMA2 operands are pre-packed.
// ============================================================================
#define BM 128
#define BN 128
#define BK 16

__global__ __launch_bounds__(256)
void gemm_ax_kernel(const float* __restrict__ x,
                    const float* __restrict__ Wx,
                    const float* __restrict__ bx,
                    int layer)
{
    const int dir = blockIdx.z;
    const float* A = (layer == 0) ? x
                                  : (g_seq + (size_t)dir * T_STEPS * BATCH * HID);
    const int wsel = 2 * layer + dir;
    const float* Bw   = Wx + (size_t)wsel * 512 * 1536;
    const float* bias = bx + (size_t)wsel * 1536;
    float* C = g_ax + (size_t)dir * 16384 * 1536;

    const int m0 = blockIdx.y * BM;
    const int n0 = blockIdx.x * BN;

    __shared__ float As[BK][BM];        //  8 KB
    __shared__ float Bs2[BK][2 * BN];   // 16 KB (each col duplicated)

    const int tid = threadIdx.x;
    // loader maps
    const int arow  = tid & 127;
    const int akseg = tid >> 7;          // 0..1 -> k offsets {0,8}
    const int bnq = tid & 31;
    const int bk  = tid >> 5;            // 0..7 -> k rows {bk, bk+8}
    // compute map
    const int tx = tid & 15;
    const int ty = tid >> 4;

    unsigned long long acc2[4][8];       // [row-pair][col], packed fp32x2
#pragma unroll
    for (int i = 0; i < 4; ++i)
#pragma unroll
        for (int j = 0; j < 8; ++j) acc2[i][j] = 0ull;

    for (int k0 = 0; k0 < 512; k0 += BK) {
        float4 a04 = *(const float4*)(A + (size_t)(m0 + arow) * 512 + k0 + akseg * 8);
        float4 a14 = *(const float4*)(A + (size_t)(m0 + arow) * 512 + k0 + akseg * 8 + 4);
        float4 bv0 = *(const float4*)(Bw + (size_t)(k0 + bk) * 1536 + n0 + bnq * 4);
        float4 bv1 = *(const float4*)(Bw + (size_t)(k0 + bk + 8) * 1536 + n0 + bnq * 4);

        As[akseg * 8 + 0][arow] = a04.x;
        As[akseg * 8 + 1][arow] = a04.y;
        As[akseg * 8 + 2][arow] = a04.z;
        As[akseg * 8 + 3][arow] = a04.w;
        As[akseg * 8 + 4][arow] = a14.x;
        As[akseg * 8 + 5][arow] = a14.y;
        As[akseg * 8 + 6][arow] = a14.z;
        As[akseg * 8 + 7][arow] = a14.w;
        float4 d0 = make_float4(bv0.x, bv0.x, bv0.y, bv0.y);
        float4 d1 = make_float4(bv0.z, bv0.z, bv0.w, bv0.w);
        float4 d2 = make_float4(bv1.x, bv1.x, bv1.y, bv1.y);
        float4 d3 = make_float4(bv1.z, bv1.z, bv1.w, bv1.w);
        *(float4*)&Bs2[bk][bnq * 8]         = d0;
        *(float4*)&Bs2[bk][bnq * 8 + 4]     = d1;
        *(float4*)&Bs2[bk + 8][bnq * 8]     = d2;
        *(float4*)&Bs2[bk + 8][bnq * 8 + 4] = d3;
        __syncthreads();

#pragma unroll
        for (int kk = 0; kk < BK; ++kk) {
            const ulonglong2 A0 = *(const ulonglong2*)&As[kk][ty * 4];
            const ulonglong2 A1 = *(const ulonglong2*)&As[kk][64 + ty * 4];
            const ulonglong2 B0 = *(const ulonglong2*)&Bs2[kk][tx * 8];
            const ulonglong2 B1 = *(const ulonglong2*)&Bs2[kk][tx * 8 + 4];
            const ulonglong2 B2 = *(const ulonglong2*)&Bs2[kk][128 + tx * 8];
            const ulonglong2 B3 = *(const ulonglong2*)&Bs2[kk][128 + tx * 8 + 4];
            const unsigned long long av[4] = {A0.x, A0.y, A1.x, A1.y};
            const unsigned long long bv[8] = {B0.x, B0.y, B1.x, B1.y,
                                              B2.x, B2.y, B3.x, B3.y};
#pragma unroll
            for (int rp = 0; rp < 4; ++rp)
#pragma unroll
                for (int j = 0; j < 8; ++j)
                    FMA2(acc2[rp][j], av[rp], bv[j]);
        }
        __syncthreads();
    }

    const float4 bb0 = *(const float4*)(bias + n0 + tx * 4);
    const float4 bb1 = *(const float4*)(bias + n0 + 64 + tx * 4);
#pragma unroll
    for (int rp = 0; rp < 4; ++rp) {
        float2 u[8];
#pragma unroll
        for (int j = 0; j < 8; ++j) u[j] = unpk(acc2[rp][j]);
        const int rbase = (rp < 2) ? (m0 + ty * 4 + rp * 2)
                                   : (m0 + 64 + ty * 4 + (rp - 2) * 2);
        float4 lo0 = make_float4(u[0].x + bb0.x, u[1].x + bb0.y,
                                 u[2].x + bb0.z, u[3].x + bb0.w);
        float4 lo1 = make_float4(u[4].x + bb1.x, u[5].x + bb1.y,
                                 u[6].x + bb1.z, u[7].x + bb1.w);
        float4 hi0 = make_float4(u[0].y + bb0.x, u[1].y + bb0.y,
                                 u[2].y + bb0.z, u[3].y + bb0.w);
        float4 hi1 = make_float4(u[4].y + bb1.x, u[5].y + bb1.y,
                                 u[6].y + bb1.z, u[7].y + bb1.w);
        *(float4*)(C + (size_t)rbase * 1536 + n0 + tx * 4)            = lo0;
        *(float4*)(C + (size_t)rbase * 1536 + n0 + 64 + tx * 4)       = lo1;
        *(float4*)(C + (size_t)(rbase + 1) * 1536 + n0 + tx * 4)      = hi0;
        *(float4*)(C + (size_t)(rbase + 1) * 1536 + n0 + 64 + tx * 4) = hi1;
    }
}

// ============================================================================
// LayerNorm over each 512-wide gate chunk of g_ax (in place), then *gx + bex.
// ============================================================================
__global__ void ln_ax_kernel(const float* __restrict__ gx,
                             const float* __restrict__ bex,
                             int layer)
{
    const int id   = blockIdx.x;
    const int gate = id % 3;
    const int row  = (id / 3) & 16383;
    const int dir  = id / (3 * 16384);
    const int wsel = 2 * layer + dir;

    float* p = g_ax + (size_t)dir * 16384 * 1536 + (size_t)row * 1536 + gate * 512;
    const float* gp = gx  + (size_t)wsel * 1536 + gate * 512;
    const float* bp = bex + (size_t)wsel * 1536 + gate * 512;

    const int tid = threadIdx.x;               // 128 threads * 4 elems
    float4 v = *(const float4*)(p + tid * 4);
    float s  = v.x + v.y + v.z + v.w;
    float ss = v.x * v.x + v.y * v.y + v.z * v.z + v.w * v.w;
#pragma unroll
    for (int o = 16; o; o >>= 1) {
        s  += __shfl_xor_sync(0xffffffffu, s,  o);
        ss += __shfl_xor_sync(0xffffffffu, ss, o);
    }
    __shared__ float red[8];
    if ((tid & 31) == 0) { red[tid >> 5] = s; red[4 + (tid >> 5)] = ss; }
    __syncthreads();
    const float ts  = red[0] + red[1] + red[2] + red[3];
    const float tss = red[4] + red[5] + red[6] + red[7];
    const float mu   = ts * (1.f / 512.f);
    const float var  = tss * (1.f / 512.f) - mu * mu;
    const float rstd = rsqrtf(var + LN_EPS);

    const float4 g4 = *(const float4*)(gp + tid * 4);
    const float4 b4 = *(const float4*)(bp + tid * 4);
    float4 o;
    o.x = (v.x - mu) * rstd * g4.x + b4.x;
    o.y = (v.y - mu) * rstd * g4.y + b4.y;
    o.z = (v.z - mu) * rstd * g4.z + b4.z;
    o.w = (v.w - mu) * rstd * g4.w + b4.w;
    *(float4*)(p + tid * 4) = o;
}

// ============================================================================
__global__ void init_scratch_kernel()
{
    const int i = threadIdx.x;
    if (i == 0) g_bar = 0u;
    for (int k = i; k < 2 * 2 * 32 * 3 * 2; k += blockDim.x) g_stats[k] = 0.f;
}

// ============================================================================
// Persistent recurrent kernel.
// 128 CTAs x 256 thr; CTA (dir,c) owns 24 weight columns (8 per gate).
// Phase A: warp owns 4 batches x all 24 cols; h read ONCE per CTA; FFMA2.
// ============================================================================
__device__ __forceinline__ void grid_bar(unsigned& target)
{
    __threadfence();
    __syncthreads();
    if (threadIdx.x == 0) {
        atomicAdd(&g_bar, 1u);
        target += (unsigned)NBLK;
        // volatile spin + nanosleep: cannot be CSE'd/deleted (side effect),
        // unlike a bare __ldcg loop (UB under forward-progress -> barrier no-op).
        while (*(volatile unsigned*)&g_bar < target) __nanosleep(20);
        __threadfence();
    }
    __syncthreads();
}

__global__ __launch_bounds__(256)
void recurrent_kernel(const float* __restrict__ Wh,
                      const float* __restrict__ bh,
                      const float* __restrict__ gh,
                      const float* __restrict__ beh,
                      const float* __restrict__ h0,
                      float* __restrict__ out,
                      int layer, int write_hid)
{
    extern __shared__ float sm[];
    float* Wsh   = sm;                         // [24][WP] col-major   12384 f
    float* hsh   = Wsh + 24 * WP;              // [32][HP]             16512 f
    float* rawsh = hsh + 32 * HP;              // [32][25]               800 f
    float* bhs   = rawsh + 32 * 25;            // 24 f
    float* ghs   = bhs + 24;                   // 24 f
    float* behs  = ghs + 24;                   // 24 f

    const int tid = threadIdx.x;
    const int cta = blockIdx.x;
    const int dir = cta >> 6;                  // 0 = fwd, 1 = bwd
    const int j0  = (cta & 63) * 8;
    const int wsel = 2 * layer + dir;

    // ---- one-time loads ----
    const float* Whd = Wh + (size_t)wsel * 512 * 1536;
    for (int i = tid; i < 24 * 512; i += 256) {
        const int c = i >> 9, k = i & 511;
        const int col = ((c >> 3) << 9) + j0 + (c & 7);
        Wsh[c * WP + k] = Whd[(size_t)k * 1536 + col];
    }
    if (tid < 24) {
        const int col = ((tid >> 3) << 9) + j0 + (tid & 7);
        bhs[tid]  = bh [(size_t)wsel * 1536 + col];
        ghs[tid]  = gh [(size_t)wsel * 1536 + col];
        behs[tid] = beh[(size_t)wsel * 1536 + col];
    }
    for (int i = tid; i < 32 * 128; i += 256) {
        const int b = i >> 7, q = i & 127;
        *(float4*)&hsh[b * HP + q * 4] =
            *(const float4*)(h0 + (size_t)wsel * 32 * 512 + b * 512 + q * 4);
    }
    __syncthreads();

    unsigned target = 0;
    // phase-A map: warp owns 4 batches; lane = colgroup(8) x b_local(4)
    const int warp = tid >> 5, lane = tid & 31;
    const int blA = lane & 3, cg = lane >> 2;
    const int bA = warp * 4 + blA;
    const int c0 = cg * 3;                     // 3 columns per lane
    // phase-B map
    const int jB = tid & 7, bB = tid >> 3;

    const float* hrow = hsh + bA * HP;
    const float* w0 = Wsh + c0 * WP;
    const float* w1 = w0 + WP;
    const float* w2 = w1 + WP;

    for (int s = 0; s < T_STEPS; ++s) {
        const int parity = s & 1;
        const int tin = dir ? (T_STEPS - 1 - s) : s;

        // prefetch ax for phase B (DRAM latency hides under phase-A GEMM)
        const float* axp = g_ax + (((size_t)dir * T_STEPS + tin) * 32 + bB) * 1536
                                + j0 + jB;
        const float axr = __ldg(axp);
        const float axz = __ldg(axp + 512);
        const float axn = __ldg(axp + 1024);

        // zero other-parity stats (safe: last read before previous step's bar2)
        if (cta == 0) {
            const int base = (parity ^ 1) * (2 * 32 * 3 * 2);
            for (int i = tid; i < 2 * 32 * 3 * 2; i += 256) g_stats[base + i] = 0.f;
        }

        // -------- Phase A: 32b x 24col GEMM via FFMA2, h read once ----------
        {
            unsigned long long p0 = 0ull, p0b = 0ull;
            unsigned long long p1 = 0ull, p1b = 0ull;
            unsigned long long p2 = 0ull, p2b = 0ull;
#pragma unroll 8
            for (int k = 0; k < 512; k += 4) {
                const ulonglong2 h2 = *(const ulonglong2*)(hrow + k);
                const ulonglong2 wa = *(const ulonglong2*)(w0 + k);
                const ulonglong2 wb = *(const ulonglong2*)(w1 + k);
                const ulonglong2 wc = *(const ulonglong2*)(w2 + k);
                FMA2(p0, h2.x, wa.x); FMA2(p0b, h2.y, wa.y);
                FMA2(p1, h2.x, wb.x); FMA2(p1b, h2.y, wb.y);
                FMA2(p2, h2.x, wc.x); FMA2(p2b, h2.y, wc.y);
            }
            const float2 q0 = unpk(p0), q0b = unpk(p0b);
            const float2 q1 = unpk(p1), q1b = unpk(p1b);
            const float2 q2 = unpk(p2), q2b = unpk(p2b);
            float* rp = rawsh + bA * 25 + c0;
            rp[0] = q0.x + q0.y + q0b.x + q0b.y + bhs[c0];
            rp[1] = q1.x + q1.y + q1b.x + q1b.y + bhs[c0 + 1];
            rp[2] = q2.x + q2.y + q2b.x + q2b.y + bhs[c0 + 2];
        }
        __syncthreads();

        // -------- LN stats from rawsh: 96 threads, one (b,gate) each ---------
        if (tid < 96) {
            const int g = tid >> 5, b = tid & 31;
            const float* rp = rawsh + b * 25 + g * 8;
            float sum = 0.f, sq = 0.f;
#pragma unroll
            for (int i = 0; i < 8; ++i) { const float v = rp[i]; sum += v; sq += v * v; }
            float* st = g_stats + ((((parity * 2 + dir) * 32 + b) * 3 + g) * 2);
            atomicAdd(st, sum);
            atomicAdd(st + 1, sq);
        }
        grid_bar(target);   // stats complete

        // -------- Phase B: normalize, gates, h_new for own 8 columns ----------
        {
            const float* st = g_stats + (((parity * 2 + dir) * 32 + bB) * 3) * 2;
            const float s0 = __ldcg(st + 0), q0 = __ldcg(st + 1);
            const float s1 = __ldcg(st + 2), q1 = __ldcg(st + 3);
            const float s2 = __ldcg(st + 4), q2 = __ldcg(st + 5);
            const float mu0 = s0 * (1.f / 512.f), v0 = q0 * (1.f / 512.f) - mu0 * mu0;
            const float mu1 = s1 * (1.f / 512.f), v1 = q1 * (1.f / 512.f) - mu1 * mu1;
            const float mu2 = s2 * (1.f / 512.f), v2 = q2 * (1.f / 512.f) - mu2 * mu2;
            const float r0 = rsqrtf(v0 + LN_EPS);
            const float r1 = rsqrtf(v1 + LN_EPS);
            const float r2 = rsqrtf(v2 + LN_EPS);

            const float* rp = rawsh + bB * 25;
            const float ahr = (rp[jB]      - mu0) * r0 * ghs[jB]      + behs[jB];
            const float ahz = (rp[8 + jB]  - mu1) * r1 * ghs[8 + jB]  + behs[8 + jB];
            const float ahn = (rp[16 + jB] - mu2) * r2 * ghs[16 + jB] + behs[16 + jB];

            const float r = 1.f / (1.f + __expf(-(axr + ahr)));
            const float z = 1.f / (1.f + __expf(-(axz + ahz)));
            const float n = tanhf(axn + r * ahn);
            const float hp = hsh[bB * HP + j0 + jB];
            const float hn = fmaf(z, hp - n, n);   // (1-z)*n + z*h

            g_h[(dir * 32 + bB) * 512 + j0 + jB] = hn;
            if (layer == 0) {
                g_seq[(size_t)dir * T_STEPS * 32 * 512
                      + ((size_t)tin * 32 + bB) * 512 + j0 + jB] = hn;
            } else {
                out[((size_t)tin * 32 + bB) * 1024 + dir * 512 + j0 + jB] = hn;
            }
            if (write_hid && s == T_STEPS - 1)
                out[(size_t)16777216 + ((size_t)wsel * 32 + bB) * 512 + j0 + jB] = hn;
        }
        grid_bar(target);   // h complete

        if (s + 1 < T_STEPS) {
            const float* hg = g_h + dir * 32 * 512;
            for (int i = tid; i < 32 * 128; i += 256) {
                const int b = i >> 7, q = i & 127;
                const float4 v = __ldcg((const float4*)(hg + b * 512 + q * 4));
                *(float4*)&hsh[b * HP + q * 4] = v;
            }
            __syncthreads();
        }
    }
}

// ============================================================================
#define RS_BYTES ((24*WP + 32*HP + 32*25 + 24*3) * 4)

extern "C" void kernel_launch(void* const* d_in, const int* in_sizes, int n_in,
                              void* d_out, int out_size)
{
    const float* x   = (const float*)d_in[0];
    const float* h0  = (const float*)d_in[1];
    const float* Wx  = (const float*)d_in[2];
    const float* Wh  = (const float*)d_in[3];
    const float* bx  = (const float*)d_in[4];
    const float* bh  = (const float*)d_in[5];
    const float* gx  = (const float*)d_in[6];
    const float* bex = (const float*)d_in[7];
    const float* gh  = (const float*)d_in[8];
    const float* beh = (const float*)d_in[9];
    float* out = (float*)d_out;

    const int write_hid = (out_size >= 16777216 + 4 * 32 * 512) ? 1 : 0;

    cudaFuncSetAttribute(recurrent_kernel,
                         cudaFuncAttributeMaxDynamicSharedMemorySize, RS_BYTES);

    for (int layer = 0; layer < 2; ++layer) {
        dim3 gg(1536 / BN, 16384 / BM, 2);
        gemm_ax_kernel<<<gg, 256>>>(x, Wx, bx, layer);
        ln_ax_kernel<<<2 * 16384 * 3, 128>>>(gx, bex, layer);
        init_scratch_kernel<<<1, 256>>>();
        recurrent_kernel<<<NBLK, 256, RS_BYTES>>>(Wh, bh, gh, beh, h0, out,
                                                  layer, write_hid);
    }
}